// round 8
// baseline (speedup 1.0000x reference)
#include <cuda_runtime.h>
#include <cstdint>

// EMA scan: s_t = 0.9*s_{t-1} + 0.1*x_t
// x: (1024, 32, 1024) f32, state: (32, 1024) f32
// out: out (1024*32768 floats) then final_state (32768 floats)
//
// Exact single pass. Kernel is LSU-issue-bound -> use 128-bit LSU ops:
// each thread owns 4 consecutive channels (LDS.128 / STG.128 / 4 FFMA
// chains). Loads decoupled via 4-stage cp.async SMEM pipeline.
// CTA = 1 warp = 128 channels; grid = 256; stage = 32 t x 128 ch = 16 KB.

#define T_STEPS 1024
#define N_CH    32768
#define CH_CTA  128
#define TT      32                     // timesteps per stage
#define STAGES  4
#define NTILES  (T_STEPS / TT)         // 32
#define STAGE_FLOATS (TT * CH_CTA)     // 4096
#define STAGE_BYTES  (STAGE_FLOATS * 4) // 16384

__device__ __forceinline__ void cp_async16(uint32_t smem_addr, const void* gmem) {
    asm volatile("cp.async.cg.shared.global [%0], [%1], 16;"
                 :: "r"(smem_addr), "l"(gmem));
}
__device__ __forceinline__ void cp_commit() {
    asm volatile("cp.async.commit_group;");
}
__device__ __forceinline__ void cp_waitN() {
    asm volatile("cp.async.wait_group %0;" :: "n"(STAGES - 2));
}

__global__ __launch_bounds__(32, 3)
void ema_scan_kernel(const float* __restrict__ x,
                     const float* __restrict__ state,
                     float* __restrict__ out)
{
    extern __shared__ float smem[];   // [STAGES][TT][CH_CTA]

    const int tid = threadIdx.x;               // 0..31
    const int c0  = blockIdx.x * CH_CTA;       // first channel of this CTA
    const int cc  = c0 + tid * 4;              // this thread's 4 channels

    uint32_t smem_base;
    asm("{ .reg .u64 t; cvta.to.shared.u64 t, %1; cvt.u32.u64 %0, t; }"
        : "=r"(smem_base) : "l"(smem));

    // one cp.async16 per thread per timestep-row: warp covers 512 B/row
    const char* gbase = (const char*)(x + (size_t)cc);

    auto issue_tile = [&](int k) {
        const uint32_t sbuf = smem_base
                            + (uint32_t)(k & (STAGES - 1)) * STAGE_BYTES
                            + (uint32_t)tid * 16;
        const char* g = gbase + (size_t)k * TT * (N_CH * 4);
        #pragma unroll
        for (int r = 0; r < TT; r++) {
            cp_async16(sbuf + (uint32_t)r * (CH_CTA * 4),
                       g + (size_t)r * (N_CH * 4));
        }
    };

    // prologue: stages 0..STAGES-2
    #pragma unroll
    for (int k = 0; k < STAGES - 1; k++) { issue_tile(k); cp_commit(); }

    float4 s = *(const float4*)(state + cc);
    float4* op = (float4*)(out + cc);

    #pragma unroll 1
    for (int k = 0; k < NTILES; k++) {
        cp_waitN();            // tile k's group complete (<= STAGES-2 pending)
        __syncwarp();          // visibility + guards buffer reuse

        if (k + STAGES - 1 < NTILES) issue_tile(k + STAGES - 1);
        cp_commit();           // keep group accounting aligned

        const float* buf = smem + (k & (STAGES - 1)) * STAGE_FLOATS + tid * 4;
        #pragma unroll
        for (int t = 0; t < TT; t++) {
            float4 xv = *(const float4*)(buf + t * CH_CTA);
            s.x = fmaf(s.x, 0.9f, xv.x * 0.1f);
            s.y = fmaf(s.y, 0.9f, xv.y * 0.1f);
            s.z = fmaf(s.z, 0.9f, xv.z * 0.1f);
            s.w = fmaf(s.w, 0.9f, xv.w * 0.1f);
            __stcs(op + (size_t)(k * TT + t) * (N_CH / 4), s);
        }
    }

    *(float4*)(out + (size_t)T_STEPS * N_CH + cc) = s;   // final_state
}

extern "C" void kernel_launch(void* const* d_in, const int* in_sizes, int n_in,
                              void* d_out, int out_size)
{
    const float* x     = (const float*)d_in[0];
    const float* state = (const float*)d_in[1];
    float*       out   = (float*)d_out;

    static bool attr_set = false;
    if (!attr_set) {
        cudaFuncSetAttribute(ema_scan_kernel,
                             cudaFuncAttributeMaxDynamicSharedMemorySize,
                             STAGES * STAGE_BYTES);
        attr_set = true;
    }

    dim3 block(32);
    dim3 grid(N_CH / CH_CTA);   // 256 CTAs
    ema_scan_kernel<<<grid, block, STAGES * STAGE_BYTES>>>(x, state, out);
}